// round 8
// baseline (speedup 1.0000x reference)
#include <cuda_runtime.h>
#include <cuda_bf16.h>
#include <cstdint>

// ---------------- problem constants ----------------
#define BT   16384
#define Gg   8
#define Dd   64
#define Vv   1024
#define GD   512
#define TM   128            // tokens per CTA
#define N_IDS (BT*Gg)
#define OUT_Q N_IDS
#define OUT_LOSS (N_IDS + BT*GD)

// 3-slot layout: [h|m|l], 3 x 64 bf16 = 192 bf16 = 24 x 16B units per row
#define KU    24
#define ROWB  384
#define CHUNK_N 64
#define NCHUNK  16
#define CHUNK_B (CHUNK_N*ROWB)   // 24576

// ---------------- smem layout (bytes) ----------------
#define SM_A    0            // 128 x 384 = 49152
#define SM_B    49152        // 2 x 24576 = 49152
#define SM_CSQ  98304        // 1024 f32
#define SM_MD   102400       // 256 f32
#define SM_MV   103424       // 256 i32
#define SM_IDS  104448       // 128 i32
#define SM_MSK  104960       // 128 f32
#define SM_RED  105472       // 8 f32
#define SMEM_TOTAL 105504

// ---------------- device globals ----------------
__device__ float g_csq[Gg*Vv];
__device__ float g_partials[Gg*(BT/TM)];
// pre-split, pre-swizzled codebook: [g][chunk][row][unit], unit u at pos u^(row&7)
__device__ __align__(16) uint4 g_cbs[Gg*Vv*KU];   // 3 MB

// ---------------- PTX helpers ----------------
__device__ __forceinline__ uint32_t smem_u32(const void* p) {
    uint32_t a;
    asm("{ .reg .u64 t; cvta.to.shared.u64 t, %1; cvt.u32.u64 %0, t; }" : "=r"(a) : "l"(p));
    return a;
}
#define LDSM4(r, addr) \
    asm volatile("ldmatrix.sync.aligned.m8n8.x4.shared.b16 {%0,%1,%2,%3}, [%4];" \
        : "=r"((r)[0]), "=r"((r)[1]), "=r"((r)[2]), "=r"((r)[3]) : "r"(addr))
#define MMA(c, a, b) \
    asm volatile("mma.sync.aligned.m16n8k16.row.col.f32.bf16.bf16.f32 " \
        "{%0,%1,%2,%3},{%4,%5,%6,%7},{%8,%9},{%0,%1,%2,%3};" \
        : "+f"((c)[0]), "+f"((c)[1]), "+f"((c)[2]), "+f"((c)[3]) \
        : "r"((a)[0]), "r"((a)[1]), "r"((a)[2]), "r"((a)[3]), "r"((b)[0]), "r"((b)[1]))
__device__ __forceinline__ void cp16(uint32_t dst, const void* src) {
    asm volatile("cp.async.cg.shared.global [%0], [%1], 16;" :: "r"(dst), "l"(src) : "memory");
}
#define CP_COMMIT()  asm volatile("cp.async.commit_group;" ::: "memory")
#define CP_WAIT(n)   asm volatile("cp.async.wait_group %0;" :: "n"(n) : "memory")

__device__ __forceinline__ void split3(float v, float& h, float& m, float& l) {
    h = __bfloat162float(__float2bfloat16_rn(v));
    float r1 = v - h;
    m = __bfloat162float(__float2bfloat16_rn(r1));
    l = r1 - m;   // bf16-rounded at pack time
}
__device__ __forceinline__ uint32_t pack_bf2(float lo, float hi) {
    uint32_t u;
    asm("cvt.rn.bf16x2.f32 %0, %1, %2;" : "=r"(u) : "f"(hi), "f"(lo));
    return u;
}

// ---------------------------------------------------------------------------
// Kernel P: split codebook into [h|m|l] swizzled rows + c_sq (fused)
// one thread per (g, v) row
// ---------------------------------------------------------------------------
__global__ void prep_kernel(const float* __restrict__ cb) {
    int idx = blockIdx.x * blockDim.x + threadIdx.x;   // 0..8191
    if (idx >= Gg * Vv) return;
    int g = idx & 7, v = idx >> 3;
    const float* src = cb + (size_t)v * GD + g * Dd;
    int c = v >> 6, r = v & 63;
    uint4* row = g_cbs + (size_t)(((g * NCHUNK + c) * CHUNK_N + r)) * KU;
    int r7 = v & 7;
    float csum = 0.f;
#pragma unroll
    for (int uu = 0; uu < 8; uu++) {
        uint32_t ph[4], pm[4], pl[4];
#pragma unroll
        for (int j = 0; j < 4; j++) {
            float a = src[uu * 8 + j * 2];
            float b = src[uu * 8 + j * 2 + 1];
            csum = fmaf(a, a, csum);
            csum = fmaf(b, b, csum);
            float ha, ma, la, hb, mb, lb;
            split3(a, ha, ma, la);
            split3(b, hb, mb, lb);
            ph[j] = pack_bf2(ha, hb);
            pm[j] = pack_bf2(ma, mb);
            pl[j] = pack_bf2(la, lb);
        }
        row[(0 * 8 + uu) ^ r7] = make_uint4(ph[0], ph[1], ph[2], ph[3]);
        row[(1 * 8 + uu) ^ r7] = make_uint4(pm[0], pm[1], pm[2], pm[3]);
        row[(2 * 8 + uu) ^ r7] = make_uint4(pl[0], pl[1], pl[2], pl[3]);
    }
    g_csq[g * Vv + v] = csum;
}

// ---------------------------------------------------------------------------
// Main VQ kernel: 256 threads, 8 warps (4 M x 2 N), 2 CTAs/SM
// 6 slot-pair passes x 4 ksteps, register-accumulated
// ---------------------------------------------------------------------------
__global__ __launch_bounds__(256, 2)
void vq_kernel(const float* __restrict__ x, const int* __restrict__ pad,
               const float* __restrict__ cb, float* __restrict__ out)
{
    extern __shared__ char sm[];
    const uint32_t sbase = smem_u32(sm);
    const int tid  = threadIdx.x;
    const int wid  = tid >> 5;
    const int lane = tid & 31;
    const int g    = blockIdx.y;
    const int bt0  = blockIdx.x * TM;
    float* csq_sm  = (float*)(sm + SM_CSQ);

    const char* cbs_g = (const char*)(g_cbs + (size_t)g * Vv * KU);

    // prefetch chunks 0 and 1 (one commit group each)
    {
        uint32_t dst = sbase + SM_B + (uint32_t)tid * 16;
        const char* src = cbs_g + (size_t)tid * 16;
#pragma unroll
        for (int i = 0; i < 6; i++) cp16(dst + i * 4096, src + i * 4096);
        CP_COMMIT();
#pragma unroll
        for (int i = 0; i < 6; i++)
            cp16(dst + CHUNK_B + i * 4096, src + CHUNK_B + i * 4096);
        CP_COMMIT();
    }

    // ---- build A: split x tile into [h|m|l], swizzled ----
    {
#pragma unroll
        for (int it = 0; it < 4; it++) {
            int idx = it * 256 + tid;          // 0..1023
            int t = idx >> 3;                  // token 0..127
            int o = idx & 7;                   // octet of 8 floats
            const float* xp = x + (size_t)(bt0 + t) * GD + g * Dd + o * 8;
            float4 v0 = *(const float4*)(xp);
            float4 v1 = *(const float4*)(xp + 4);
            float h0,m0,l0,h1,m1,l1,h2,m2,l2,h3,m3,l3;
            float h4,m4,l4,h5,m5,l5,h6,m6,l6,h7,m7,l7;
            split3(v0.x,h0,m0,l0); split3(v0.y,h1,m1,l1);
            split3(v0.z,h2,m2,l2); split3(v0.w,h3,m3,l3);
            split3(v1.x,h4,m4,l4); split3(v1.y,h5,m5,l5);
            split3(v1.z,h6,m6,l6); split3(v1.w,h7,m7,l7);
            uint4 H = make_uint4(pack_bf2(h0,h1), pack_bf2(h2,h3), pack_bf2(h4,h5), pack_bf2(h6,h7));
            uint4 M = make_uint4(pack_bf2(m0,m1), pack_bf2(m2,m3), pack_bf2(m4,m5), pack_bf2(m6,m7));
            uint4 L = make_uint4(pack_bf2(l0,l1), pack_bf2(l2,l3), pack_bf2(l4,l5), pack_bf2(l6,l7));
            int r7 = t & 7;
            uint4* arow = (uint4*)(sm + SM_A + t * ROWB);
            arow[(0 * 8 + o) ^ r7] = H;
            arow[(1 * 8 + o) ^ r7] = M;
            arow[(2 * 8 + o) ^ r7] = L;
        }
    }
    for (int i = tid; i < Vv; i += 256) csq_sm[i] = g_csq[g * Vv + i];
    __syncthreads();

    // ---- per-warp geometry ----
    const int wm = (wid & 3) * 32;      // warp M base
    const int wn = (wid >> 2) * 32;     // warp N base within 64-wide chunk
    const int lq = lane >> 3;
    const int lr = lane & 7;
    const uint32_t aptr0 = sbase + SM_A + (uint32_t)(wm + (lq & 1) * 8 + lr) * ROWB;
    const uint32_t aptr1 = aptr0 + 16 * ROWB;
    const int aksel = lq >> 1;
    const int bksel = lq & 1;
    const uint32_t brow = (uint32_t)(wn + (lq >> 1) * 8 + lr) * ROWB;

    // slot-pair schedule: products hh', hm', mh', hl', lh', mm'
    const int PA0=0,PB0=0, PA1=0,PB1=1, PA2=1,PB2=0, PA3=0,PB3=2, PA4=2,PB4=0, PA5=1,PB5=1;

    float mind[4];
    int   minv[4];
#pragma unroll
    for (int s = 0; s < 4; s++) { mind[s] = __int_as_float(0x7f800000); minv[s] = 0; }

    for (int c = 0; c < NCHUNK; c++) {
        if (c >= 1 && c + 1 < NCHUNK) {
            uint32_t dst = sbase + SM_B + (uint32_t)(((c + 1) & 1) * CHUNK_B) + (uint32_t)tid * 16;
            const char* src = cbs_g + (size_t)(c + 1) * CHUNK_B + (size_t)tid * 16;
#pragma unroll
            for (int i = 0; i < 6; i++) cp16(dst + i * 4096, src + i * 4096);
            CP_COMMIT();
        }
        if (c + 1 < NCHUNK) { CP_WAIT(1); } else { CP_WAIT(0); }
        __syncthreads();

        float cc[2][4][4];
#pragma unroll
        for (int mt = 0; mt < 2; mt++)
#pragma unroll
            for (int nt = 0; nt < 4; nt++)
#pragma unroll
                for (int r = 0; r < 4; r++) cc[mt][nt][r] = 0.f;

        const uint32_t bptr0 = sbase + SM_B + (uint32_t)((c & 1) * CHUNK_B) + brow;
        const uint32_t bptr1 = bptr0 + 16 * ROWB;

#pragma unroll
        for (int pp = 0; pp < 6; pp++) {
            const int pa = (pp==0?PA0:pp==1?PA1:pp==2?PA2:pp==3?PA3:pp==4?PA4:PA5);
            const int pb = (pp==0?PB0:pp==1?PB1:pp==2?PB2:pp==3?PB3:pp==4?PB4:PB5);
#pragma unroll
            for (int k = 0; k < 4; k++) {
                uint32_t ua = (uint32_t)(((pa * 8 + 2 * k + aksel) ^ lr) << 4);
                uint32_t ub = (uint32_t)(((pb * 8 + 2 * k + bksel) ^ lr) << 4);
                uint32_t a[8], b[8];
                LDSM4(a + 0, aptr0 + ua);
                LDSM4(a + 4, aptr1 + ua);
                LDSM4(b + 0, bptr0 + ub);
                LDSM4(b + 4, bptr1 + ub);
#pragma unroll
                for (int mt = 0; mt < 2; mt++) {
                    MMA(cc[mt][0], a + mt * 4, b + 0);
                    MMA(cc[mt][1], a + mt * 4, b + 2);
                    MMA(cc[mt][2], a + mt * 4, b + 4);
                    MMA(cc[mt][3], a + mt * 4, b + 6);
                }
            }
        }

        // dist = csq - 2*dot; running argmin (ascending v for deterministic ties)
        const int colb = c * CHUNK_N + wn + 2 * (lane & 3);
#pragma unroll
        for (int nt = 0; nt < 4; nt++) {
            int v0 = colb + nt * 8;
            float q0 = csq_sm[v0], q1 = csq_sm[v0 + 1];
#pragma unroll
            for (int mt = 0; mt < 2; mt++) {
                float d0 = fmaf(-2.f, cc[mt][nt][0], q0);
                float d1 = fmaf(-2.f, cc[mt][nt][1], q1);
                float d2 = fmaf(-2.f, cc[mt][nt][2], q0);
                float d3 = fmaf(-2.f, cc[mt][nt][3], q1);
                int s0 = mt * 2, s1 = mt * 2 + 1;
                if (d0 < mind[s0]) { mind[s0] = d0; minv[s0] = v0; }
                if (d1 < mind[s0]) { mind[s0] = d1; minv[s0] = v0 + 1; }
                if (d2 < mind[s1]) { mind[s1] = d2; minv[s1] = v0; }
                if (d3 < mind[s1]) { mind[s1] = d3; minv[s1] = v0 + 1; }
            }
        }
        __syncthreads();   // compute done before next prefetch overwrites buffer
    }

    // ---- reduce within lane-quads (same token row), write per-N-half ----
#pragma unroll
    for (int s = 0; s < 4; s++) {
        float d = mind[s]; int v = minv[s];
        float d2 = __shfl_xor_sync(0xffffffffu, d, 1);
        int   v2 = __shfl_xor_sync(0xffffffffu, v, 1);
        if (d2 < d || (d2 == d && v2 < v)) { d = d2; v = v2; }
        d2 = __shfl_xor_sync(0xffffffffu, d, 2);
        v2 = __shfl_xor_sync(0xffffffffu, v, 2);
        if (d2 < d || (d2 == d && v2 < v)) { d = d2; v = v2; }
        if ((lane & 3) == 0) {
            int row = wm + (s >> 1) * 16 + (s & 1) * 8 + (lane >> 2);
            ((float*)(sm + SM_MD))[(wid >> 2) * 128 + row] = d;
            ((int*)  (sm + SM_MV))[(wid >> 2) * 128 + row] = v;
        }
    }
    __syncthreads();

    // ---- combine N-halves, emit ids + mask ----
    if (tid < TM) {
        float d0 = ((float*)(sm + SM_MD))[tid];
        float d1 = ((float*)(sm + SM_MD))[128 + tid];
        int   v0 = ((int*)(sm + SM_MV))[tid];
        int   v1 = ((int*)(sm + SM_MV))[128 + tid];
        int v = (d1 < d0 || (d1 == d0 && v1 < v0)) ? v1 : v0;
        int bt = bt0 + tid;
        int p  = pad[bt];
        ((int*)(sm + SM_IDS))[tid]   = v;
        ((float*)(sm + SM_MSK))[tid] = p ? 0.f : 1.f;
        out[(size_t)bt * Gg + g] = p ? -1.0f : (float)v;
    }
    __syncthreads();

    // ---- quantized = q*mask + masked ||q-x||^2 partial (exact f32 from global) ----
    float ss = 0.f;
    {
        int tk = tid >> 1, hf = tid & 1, d0 = hf * 32;
        int id  = ((int*)(sm + SM_IDS))[tk];
        float m = ((float*)(sm + SM_MSK))[tk];
        int bt  = bt0 + tk;
        const float* qc = cb + (size_t)id * GD + g * Dd + d0;
        const float* xr = x  + (size_t)bt * GD + g * Dd + d0;
        float* qo = out + OUT_Q + ((size_t)bt * Gg + g) * Dd + d0;
#pragma unroll
        for (int q4 = 0; q4 < 8; q4++) {
            float4 qv = *(const float4*)(qc + q4 * 4);
            float4 xv = *(const float4*)(xr + q4 * 4);
            float e0 = qv.x - xv.x, e1 = qv.y - xv.y, e2 = qv.z - xv.z, e3 = qv.w - xv.w;
            ss += e0*e0 + e1*e1 + e2*e2 + e3*e3;
            float4 o; o.x = qv.x*m; o.y = qv.y*m; o.z = qv.z*m; o.w = qv.w*m;
            *(float4*)(qo + q4 * 4) = o;
        }
        ss *= m;
    }
    for (int off = 16; off; off >>= 1) ss += __shfl_down_sync(0xffffffffu, ss, off);
    if ((tid & 31) == 0) ((float*)(sm + SM_RED))[wid] = ss;
    __syncthreads();
    if (tid == 0) {
        float s = 0.f;
#pragma unroll
        for (int i = 0; i < 8; i++) s += ((float*)(sm + SM_RED))[i];
        g_partials[g * gridDim.x + blockIdx.x] = s;
    }
}

// ---------------------------------------------------------------------------
// Final reduction
// ---------------------------------------------------------------------------
__global__ void final_kernel(const int* __restrict__ pad, float* __restrict__ out) {
    __shared__ float rs[1024];
    __shared__ int   rc[1024];
    int tid = threadIdx.x;
    float s = (tid < Gg * (BT / TM)) ? g_partials[tid] : 0.f;
    int c = 0;
    const int4* p4 = (const int4*)pad;
#pragma unroll
    for (int i = 0; i < 4; i++) {
        int4 v = p4[i * 1024 + tid];
        c += (v.x == 0) + (v.y == 0) + (v.z == 0) + (v.w == 0);
    }
    rs[tid] = s; rc[tid] = c;
    __syncthreads();
    for (int off = 512; off; off >>= 1) {
        if (tid < off) { rs[tid] += rs[tid + off]; rc[tid] += rc[tid + off]; }
        __syncthreads();
    }
    if (tid == 0) {
        float k = rs[0] / (float)rc[0];
        out[OUT_LOSS + 0] = k;
        out[OUT_LOSS + 1] = k;
        out[OUT_LOSS + 2] = k + k;
    }
}

// ---------------------------------------------------------------------------
extern "C" void kernel_launch(void* const* d_in, const int* in_sizes, int n_in,
                              void* d_out, int out_size)
{
    const float* x   = (const float*)d_in[0];
    const int*   pad = (const int*)  d_in[1];
    const float* cb  = (const float*)d_in[2];
    float*       out = (float*)d_out;

    cudaFuncSetAttribute(vq_kernel, cudaFuncAttributeMaxDynamicSharedMemorySize, SMEM_TOTAL);

    prep_kernel<<<32, 256>>>(cb);
    dim3 grid(BT / TM, Gg);
    vq_kernel<<<grid, 256, SMEM_TOTAL>>>(x, pad, cb, out);
    final_kernel<<<1, 1024>>>(pad, out);
}

// round 9
// speedup vs baseline: 1.3250x; 1.3250x over previous
#include <cuda_runtime.h>
#include <cuda_bf16.h>
#include <cstdint>

// ---------------- problem constants ----------------
#define BT   16384
#define Gg   8
#define Dd   64
#define Vv   1024
#define GD   512
#define TM   128            // tokens per CTA
#define N_IDS (BT*Gg)
#define OUT_Q N_IDS
#define OUT_LOSS (N_IDS + BT*GD)
#define DELTA 0.012f

// 3-slot extended-K layout: A=[h|h|m], B=[h'|m'|h'], 3 x 64 bf16 = 24 x 16B/row
#define KU    24
#define ROWB  384
#define NKS   12
#define CHUNK_N 64
#define NCHUNK  16
#define CHUNK_B (CHUNK_N*ROWB)   // 24576

// ---------------- smem layout (bytes) ----------------
#define SM_A    0            // 128 x 384 = 49152
#define SM_B    49152        // 2 x 24576 = 49152
#define SM_CSQ  98304        // 1024 f32
#define SM_MD   102400       // 256 f32
#define SM_MV   103424       // 256 i32
#define SM_MD2  104448       // 256 f32
#define SMEM_TOTAL 105472

// ---------------- device globals ----------------
__device__ float g_csq[Gg*Vv];
__device__ float g_partials[4096];
__device__ int   g_ids [BT*Gg];
__device__ int   g_flag[BT*Gg];
__device__ __align__(16) uint4 g_cbs[Gg*Vv*KU];   // 3 MB

// ---------------- PTX helpers ----------------
__device__ __forceinline__ uint32_t smem_u32(const void* p) {
    uint32_t a;
    asm("{ .reg .u64 t; cvta.to.shared.u64 t, %1; cvt.u32.u64 %0, t; }" : "=r"(a) : "l"(p));
    return a;
}
#define LDSM4(r, addr) \
    asm volatile("ldmatrix.sync.aligned.m8n8.x4.shared.b16 {%0,%1,%2,%3}, [%4];" \
        : "=r"((r)[0]), "=r"((r)[1]), "=r"((r)[2]), "=r"((r)[3]) : "r"(addr))
#define MMA(c, a, b) \
    asm volatile("mma.sync.aligned.m16n8k16.row.col.f32.bf16.bf16.f32 " \
        "{%0,%1,%2,%3},{%4,%5,%6,%7},{%8,%9},{%0,%1,%2,%3};" \
        : "+f"((c)[0]), "+f"((c)[1]), "+f"((c)[2]), "+f"((c)[3]) \
        : "r"((a)[0]), "r"((a)[1]), "r"((a)[2]), "r"((a)[3]), "r"((b)[0]), "r"((b)[1]))
__device__ __forceinline__ void cp16(uint32_t dst, const void* src) {
    asm volatile("cp.async.cg.shared.global [%0], [%1], 16;" :: "r"(dst), "l"(src) : "memory");
}
#define CP_COMMIT()  asm volatile("cp.async.commit_group;" ::: "memory")
#define CP_WAIT(n)   asm volatile("cp.async.wait_group %0;" :: "n"(n) : "memory")

__device__ __forceinline__ void split2(float v, float& h, float& m) {
    h = __bfloat162float(__float2bfloat16_rn(v));
    m = v - h;   // bf16-rounded at pack time
}
__device__ __forceinline__ uint32_t pack_bf2(float lo, float hi) {
    uint32_t u;
    asm("cvt.rn.bf16x2.f32 %0, %1, %2;" : "=r"(u) : "f"(hi), "f"(lo));
    return u;
}

// ---------------------------------------------------------------------------
// Kernel P: split codebook into [h'|m'|h'] swizzled rows + c_sq (fused)
// ---------------------------------------------------------------------------
__global__ void prep_kernel(const float* __restrict__ cb) {
    int idx = blockIdx.x * blockDim.x + threadIdx.x;   // 0..8191
    if (idx >= Gg * Vv) return;
    int g = idx & 7, v = idx >> 3;
    const float* src = cb + (size_t)v * GD + g * Dd;
    int c = v >> 6, r = v & 63;
    uint4* row = g_cbs + (size_t)(((g * NCHUNK + c) * CHUNK_N + r)) * KU;
    int r7 = v & 7;
    float csum = 0.f;
#pragma unroll
    for (int uu = 0; uu < 8; uu++) {
        uint32_t ph[4], pm[4];
#pragma unroll
        for (int j = 0; j < 4; j++) {
            float a = src[uu * 8 + j * 2];
            float b = src[uu * 8 + j * 2 + 1];
            csum = fmaf(a, a, csum);
            csum = fmaf(b, b, csum);
            float ha, ma, hb, mb;
            split2(a, ha, ma);
            split2(b, hb, mb);
            ph[j] = pack_bf2(ha, hb);
            pm[j] = pack_bf2(ma, mb);
        }
        uint4 H = make_uint4(ph[0], ph[1], ph[2], ph[3]);
        uint4 M = make_uint4(pm[0], pm[1], pm[2], pm[3]);
        row[(0 * 8 + uu) ^ r7] = H;   // slot0: h'
        row[(1 * 8 + uu) ^ r7] = M;   // slot1: m'
        row[(2 * 8 + uu) ^ r7] = H;   // slot2: h'
    }
    g_csq[g * Vv + v] = csum;
}

// ---------------------------------------------------------------------------
// Main VQ kernel: 3-product approx GEMM + top-2 argmin + flag
// ---------------------------------------------------------------------------
__global__ __launch_bounds__(256, 2)
void vq_kernel(const float* __restrict__ x)
{
    extern __shared__ char sm[];
    const uint32_t sbase = smem_u32(sm);
    const int tid  = threadIdx.x;
    const int wid  = tid >> 5;
    const int lane = tid & 31;
    const int g    = blockIdx.y;
    const int bt0  = blockIdx.x * TM;
    float* csq_sm  = (float*)(sm + SM_CSQ);

    const char* cbs_g = (const char*)(g_cbs + (size_t)g * Vv * KU);

    // prefetch chunks 0 and 1
    {
        uint32_t dst = sbase + SM_B + (uint32_t)tid * 16;
        const char* src = cbs_g + (size_t)tid * 16;
#pragma unroll
        for (int i = 0; i < 6; i++) cp16(dst + i * 4096, src + i * 4096);
        CP_COMMIT();
#pragma unroll
        for (int i = 0; i < 6; i++)
            cp16(dst + CHUNK_B + i * 4096, src + CHUNK_B + i * 4096);
        CP_COMMIT();
    }

    // ---- build A: x tile -> [h|h|m], swizzled ----
    {
#pragma unroll
        for (int it = 0; it < 4; it++) {
            int idx = it * 256 + tid;          // 0..1023
            int t = idx >> 3;                  // token 0..127
            int o = idx & 7;                   // octet of 8 floats
            const float* xp = x + (size_t)(bt0 + t) * GD + g * Dd + o * 8;
            float4 v0 = *(const float4*)(xp);
            float4 v1 = *(const float4*)(xp + 4);
            float h0,m0,h1,m1,h2,m2,h3,m3,h4,m4,h5,m5,h6,m6,h7,m7;
            split2(v0.x,h0,m0); split2(v0.y,h1,m1);
            split2(v0.z,h2,m2); split2(v0.w,h3,m3);
            split2(v1.x,h4,m4); split2(v1.y,h5,m5);
            split2(v1.z,h6,m6); split2(v1.w,h7,m7);
            uint4 H = make_uint4(pack_bf2(h0,h1), pack_bf2(h2,h3), pack_bf2(h4,h5), pack_bf2(h6,h7));
            uint4 M = make_uint4(pack_bf2(m0,m1), pack_bf2(m2,m3), pack_bf2(m4,m5), pack_bf2(m6,m7));
            int r7 = t & 7;
            uint4* arow = (uint4*)(sm + SM_A + t * ROWB);
            arow[(0 * 8 + o) ^ r7] = H;   // slot0: h
            arow[(1 * 8 + o) ^ r7] = H;   // slot1: h
            arow[(2 * 8 + o) ^ r7] = M;   // slot2: m
        }
    }
    for (int i = tid; i < Vv; i += 256) csq_sm[i] = g_csq[g * Vv + i];
    __syncthreads();

    // ---- per-warp geometry ----
    const int wm = (wid & 3) * 32;
    const int wn = (wid >> 2) * 32;
    const int lq = lane >> 3;
    const int lr = lane & 7;
    const uint32_t aptr0 = sbase + SM_A + (uint32_t)(wm + (lq & 1) * 8 + lr) * ROWB;
    const uint32_t aptr1 = aptr0 + 16 * ROWB;
    const int aksel = lq >> 1;
    const int bksel = lq & 1;
    const uint32_t brow = (uint32_t)(wn + (lq >> 1) * 8 + lr) * ROWB;

    float mind[4], mind2[4];
    int   minv[4];
#pragma unroll
    for (int s = 0; s < 4; s++) {
        mind[s] = __int_as_float(0x7f800000);
        mind2[s] = __int_as_float(0x7f800000);
        minv[s] = 0;
    }

    for (int c = 0; c < NCHUNK; c++) {
        if (c >= 1 && c + 1 < NCHUNK) {
            uint32_t dst = sbase + SM_B + (uint32_t)(((c + 1) & 1) * CHUNK_B) + (uint32_t)tid * 16;
            const char* src = cbs_g + (size_t)(c + 1) * CHUNK_B + (size_t)tid * 16;
#pragma unroll
            for (int i = 0; i < 6; i++) cp16(dst + i * 4096, src + i * 4096);
            CP_COMMIT();
        }
        if (c + 1 < NCHUNK) { CP_WAIT(1); } else { CP_WAIT(0); }
        __syncthreads();

        float cc[2][4][4];
#pragma unroll
        for (int mt = 0; mt < 2; mt++)
#pragma unroll
            for (int nt = 0; nt < 4; nt++)
#pragma unroll
                for (int r = 0; r < 4; r++) cc[mt][nt][r] = 0.f;

        const uint32_t bptr0 = sbase + SM_B + (uint32_t)((c & 1) * CHUNK_B) + brow;
        const uint32_t bptr1 = bptr0 + 16 * ROWB;
#pragma unroll
        for (int ks = 0; ks < NKS; ks++) {
            uint32_t ua = (uint32_t)(((2 * ks + aksel) ^ lr) << 4);
            uint32_t ub = (uint32_t)(((2 * ks + bksel) ^ lr) << 4);
            uint32_t a[8], b[8];
            LDSM4(a + 0, aptr0 + ua);
            LDSM4(a + 4, aptr1 + ua);
            LDSM4(b + 0, bptr0 + ub);
            LDSM4(b + 4, bptr1 + ub);
#pragma unroll
            for (int mt = 0; mt < 2; mt++) {
                MMA(cc[mt][0], a + mt * 4, b + 0);
                MMA(cc[mt][1], a + mt * 4, b + 2);
                MMA(cc[mt][2], a + mt * 4, b + 4);
                MMA(cc[mt][3], a + mt * 4, b + 6);
            }
        }

        // dist = csq - 2*dot; running top-2 (ascending v, strict <)
        const int colb = c * CHUNK_N + wn + 2 * (lane & 3);
#pragma unroll
        for (int nt = 0; nt < 4; nt++) {
            int v0 = colb + nt * 8;
            float q0 = csq_sm[v0], q1 = csq_sm[v0 + 1];
#pragma unroll
            for (int mt = 0; mt < 2; mt++) {
                float d0 = fmaf(-2.f, cc[mt][nt][0], q0);
                float d1 = fmaf(-2.f, cc[mt][nt][1], q1);
                float d2 = fmaf(-2.f, cc[mt][nt][2], q0);
                float d3 = fmaf(-2.f, cc[mt][nt][3], q1);
                int s0 = mt * 2, s1 = mt * 2 + 1;
                if (d0 < mind[s0]) { mind2[s0] = mind[s0]; mind[s0] = d0; minv[s0] = v0; }
                else if (d0 < mind2[s0]) mind2[s0] = d0;
                if (d1 < mind[s0]) { mind2[s0] = mind[s0]; mind[s0] = d1; minv[s0] = v0 + 1; }
                else if (d1 < mind2[s0]) mind2[s0] = d1;
                if (d2 < mind[s1]) { mind2[s1] = mind[s1]; mind[s1] = d2; minv[s1] = v0; }
                else if (d2 < mind2[s1]) mind2[s1] = d2;
                if (d3 < mind[s1]) { mind2[s1] = mind[s1]; mind[s1] = d3; minv[s1] = v0 + 1; }
                else if (d3 < mind2[s1]) mind2[s1] = d3;
            }
        }
        __syncthreads();
    }

    // ---- top-2 reduce within lane-quads, write per-N-half ----
#pragma unroll
    for (int s = 0; s < 4; s++) {
        float d = mind[s], d2v = mind2[s];
        int v = minv[s];
#pragma unroll
        for (int off = 1; off <= 2; off <<= 1) {
            float o1 = __shfl_xor_sync(0xffffffffu, d, off);
            int   ov = __shfl_xor_sync(0xffffffffu, v, off);
            float o2 = __shfl_xor_sync(0xffffffffu, d2v, off);
            float big = fmaxf(d, o1);
            d2v = fminf(fminf(d2v, o2), big);
            if (o1 < d || (o1 == d && ov < v)) { d = o1; v = ov; }
        }
        if ((lane & 3) == 0) {
            int row = wm + (s >> 1) * 16 + (s & 1) * 8 + (lane >> 2);
            ((float*)(sm + SM_MD ))[(wid >> 2) * 128 + row] = d;
            ((int*)  (sm + SM_MV ))[(wid >> 2) * 128 + row] = v;
            ((float*)(sm + SM_MD2))[(wid >> 2) * 128 + row] = d2v;
        }
    }
    __syncthreads();

    // ---- combine N-halves, emit id + flag ----
    if (tid < TM) {
        float a1 = ((float*)(sm + SM_MD))[tid];
        float b1 = ((float*)(sm + SM_MD))[128 + tid];
        float a2 = ((float*)(sm + SM_MD2))[tid];
        float b2 = ((float*)(sm + SM_MD2))[128 + tid];
        int av = ((int*)(sm + SM_MV))[tid];
        int bv = ((int*)(sm + SM_MV))[128 + tid];
        float m1; int v1;
        if (b1 < a1 || (b1 == a1 && bv < av)) { m1 = b1; v1 = bv; }
        else                                  { m1 = a1; v1 = av; }
        float big = fmaxf(a1, b1);
        float m2  = fminf(fminf(a2, b2), big);
        int p = (bt0 + tid) * Gg + g;
        g_ids [p] = v1;
        g_flag[p] = (m2 - m1 < DELTA) ? 1 : 0;
    }
}

// ---------------------------------------------------------------------------
// Epilogue: exact-fallback for flagged pairs, ids/quantized/loss
// 8 threads per (token, g) pair; grid 4096 x 256
// ---------------------------------------------------------------------------
__global__ __launch_bounds__(256)
void epi_kernel(const float* __restrict__ x, const int* __restrict__ pad,
                const float* __restrict__ cb, float* __restrict__ out)
{
    __shared__ float rs[256];
    const int tid  = threadIdx.x;
    const int gidx = blockIdx.x * 256 + tid;
    const int p    = gidx >> 3;
    const int sub  = gidx & 7;
    const int bt   = p >> 3;
    const int g    = p & 7;

    int id = g_ids[p];
    if (g_flag[p]) {
        // exact fp32 argmin over all 1024 codewords, 8 lanes cooperate
        float xr[64];
        const float4* xp4 = (const float4*)(x + (size_t)bt * GD + g * Dd);
#pragma unroll
        for (int i = 0; i < 16; i++) {
            float4 v = xp4[i];
            xr[i*4] = v.x; xr[i*4+1] = v.y; xr[i*4+2] = v.z; xr[i*4+3] = v.w;
        }
        float bd = __int_as_float(0x7f800000);
        int bv = 0;
        for (int v = sub * 128; v < sub * 128 + 128; v++) {
            const float4* cp4 = (const float4*)(cb + (size_t)v * GD + g * Dd);
            float dot = 0.f;
#pragma unroll
            for (int i = 0; i < 16; i++) {
                float4 cv = cp4[i];
                dot = fmaf(cv.x, xr[i*4],   dot);
                dot = fmaf(cv.y, xr[i*4+1], dot);
                dot = fmaf(cv.z, xr[i*4+2], dot);
                dot = fmaf(cv.w, xr[i*4+3], dot);
            }
            float d = fmaf(-2.f, dot, g_csq[g * Vv + v]);
            if (d < bd) { bd = d; bv = v; }
        }
        unsigned msk = 0xFFu << ((tid & 31) & ~7);
#pragma unroll
        for (int off = 1; off <= 4; off <<= 1) {
            float od = __shfl_xor_sync(msk, bd, off);
            int   ov = __shfl_xor_sync(msk, bv, off);
            if (od < bd || (od == bd && ov < bv)) { bd = od; bv = ov; }
        }
        id = bv;
    }

    int pv = pad[bt];
    float m = pv ? 0.f : 1.f;
    if (sub == 0) out[p] = pv ? -1.0f : (float)id;

    // quantized = q*mask + masked ||q - x||^2 partial (8 dims per thread)
    float ss = 0.f;
    {
        int d0 = sub * 8;
        const float* qc = cb + (size_t)id * GD + g * Dd + d0;
        const float* xr = x  + (size_t)bt * GD + g * Dd + d0;
        float* qo = out + OUT_Q + (size_t)p * Dd + d0;
#pragma unroll
        for (int q4 = 0; q4 < 2; q4++) {
            float4 qv = *(const float4*)(qc + q4 * 4);
            float4 xv = *(const float4*)(xr + q4 * 4);
            float e0 = qv.x - xv.x, e1 = qv.y - xv.y, e2 = qv.z - xv.z, e3 = qv.w - xv.w;
            ss += e0*e0 + e1*e1 + e2*e2 + e3*e3;
            float4 o; o.x = qv.x*m; o.y = qv.y*m; o.z = qv.z*m; o.w = qv.w*m;
            *(float4*)(qo + q4 * 4) = o;
        }
        ss *= m;
    }
    rs[tid] = ss;
    __syncthreads();
    for (int off = 128; off; off >>= 1) {
        if (tid < off) rs[tid] += rs[tid + off];
        __syncthreads();
    }
    if (tid == 0) g_partials[blockIdx.x] = rs[0];
}

// ---------------------------------------------------------------------------
// Final reduction
// ---------------------------------------------------------------------------
__global__ void final_kernel(const int* __restrict__ pad, float* __restrict__ out) {
    __shared__ float rs[1024];
    __shared__ int   rc[1024];
    int tid = threadIdx.x;
    float s = 0.f;
#pragma unroll
    for (int i = 0; i < 4; i++) s += g_partials[i * 1024 + tid];
    int c = 0;
    const int4* p4 = (const int4*)pad;
#pragma unroll
    for (int i = 0; i < 4; i++) {
        int4 v = p4[i * 1024 + tid];
        c += (v.x == 0) + (v.y == 0) + (v.z == 0) + (v.w == 0);
    }
    rs[tid] = s; rc[tid] = c;
    __syncthreads();
    for (int off = 512; off; off >>= 1) {
        if (tid < off) { rs[tid] += rs[tid + off]; rc[tid] += rc[tid + off]; }
        __syncthreads();
    }
    if (tid == 0) {
        float k = rs[0] / (float)rc[0];
        out[OUT_LOSS + 0] = k;
        out[OUT_LOSS + 1] = k;
        out[OUT_LOSS + 2] = k + k;
    }
}

// ---------------------------------------------------------------------------
extern "C" void kernel_launch(void* const* d_in, const int* in_sizes, int n_in,
                              void* d_out, int out_size)
{
    const float* x   = (const float*)d_in[0];
    const int*   pad = (const int*)  d_in[1];
    const float* cb  = (const float*)d_in[2];
    float*       out = (float*)d_out;

    cudaFuncSetAttribute(vq_kernel, cudaFuncAttributeMaxDynamicSharedMemorySize, SMEM_TOTAL);

    prep_kernel<<<32, 256>>>(cb);
    dim3 grid(BT / TM, Gg);
    vq_kernel<<<grid, 256, SMEM_TOTAL>>>(x);
    epi_kernel<<<4096, 256>>>(x, pad, cb, out);
    final_kernel<<<1, 1024>>>(pad, out);
}

// round 10
// speedup vs baseline: 2.1022x; 1.5866x over previous
#include <cuda_runtime.h>
#include <cuda_bf16.h>
#include <cstdint>

// ---------------- problem constants ----------------
#define BT   16384
#define Gg   8
#define Dd   64
#define Vv   1024
#define GD   512
#define TM   128            // tokens per CTA
#define N_IDS (BT*Gg)
#define OUT_Q N_IDS
#define OUT_LOSS (N_IDS + BT*GD)
#define DELTA 0.012f

// 3-slot extended-K layout: A=[h|h|m], B=[h'|m'|h'], 3 x 64 bf16 = 24 x 16B/row
#define KU    24
#define ROWB  384
#define NKS   12
#define CHUNK_N 64
#define NCHUNK  16
#define CHUNK_B (CHUNK_N*ROWB)   // 24576

// ---------------- smem layout (bytes) ----------------
#define SM_A    0            // 128 x 384 = 49152
#define SM_B    49152        // 2 x 24576 = 49152
#define SM_CSQ  98304        // 1024 f32
#define SM_MD   102400       // 256 f32
#define SM_MV   103424       // 256 i32
#define SM_MD2  104448       // 256 f32
#define SMEM_TOTAL 105472

// ---------------- device globals ----------------
__device__ float g_csq[Gg*Vv];
__device__ float g_partials[4096];
__device__ int   g_ids [BT*Gg];
__device__ int   g_flag[BT*Gg];
__device__ int   g_list[BT];
__device__ int   g_cnt;
__device__ __align__(16) uint4 g_cbs[Gg*Vv*KU];   // 3 MB

// ---------------- PTX helpers ----------------
__device__ __forceinline__ uint32_t smem_u32(const void* p) {
    uint32_t a;
    asm("{ .reg .u64 t; cvta.to.shared.u64 t, %1; cvt.u32.u64 %0, t; }" : "=r"(a) : "l"(p));
    return a;
}
#define LDSM4(r, addr) \
    asm volatile("ldmatrix.sync.aligned.m8n8.x4.shared.b16 {%0,%1,%2,%3}, [%4];" \
        : "=r"((r)[0]), "=r"((r)[1]), "=r"((r)[2]), "=r"((r)[3]) : "r"(addr))
#define MMA(c, a, b) \
    asm volatile("mma.sync.aligned.m16n8k16.row.col.f32.bf16.bf16.f32 " \
        "{%0,%1,%2,%3},{%4,%5,%6,%7},{%8,%9},{%0,%1,%2,%3};" \
        : "+f"((c)[0]), "+f"((c)[1]), "+f"((c)[2]), "+f"((c)[3]) \
        : "r"((a)[0]), "r"((a)[1]), "r"((a)[2]), "r"((a)[3]), "r"((b)[0]), "r"((b)[1]))
__device__ __forceinline__ void cp16(uint32_t dst, const void* src) {
    asm volatile("cp.async.cg.shared.global [%0], [%1], 16;" :: "r"(dst), "l"(src) : "memory");
}
#define CP_COMMIT()  asm volatile("cp.async.commit_group;" ::: "memory")
#define CP_WAIT(n)   asm volatile("cp.async.wait_group %0;" :: "n"(n) : "memory")

__device__ __forceinline__ void split2(float v, float& h, float& m) {
    h = __bfloat162float(__float2bfloat16_rn(v));
    m = v - h;   // bf16-rounded at pack time
}
__device__ __forceinline__ uint32_t pack_bf2(float lo, float hi) {
    uint32_t u;
    asm("cvt.rn.bf16x2.f32 %0, %1, %2;" : "=r"(u) : "f"(hi), "f"(lo));
    return u;
}

// ---------------------------------------------------------------------------
// Kernel S: deterministic compaction of valid tokens (ascending order)
// 1 block, 1024 threads, 16 tokens each
// ---------------------------------------------------------------------------
__global__ void scan_kernel(const int* __restrict__ pad) {
    __shared__ int sc[1024];
    __shared__ int s_total;
    const int tid = threadIdx.x;
    int loc[16];
    int c = 0;
#pragma unroll
    for (int i = 0; i < 16; i++) {
        loc[i] = pad[tid * 16 + i];
        c += (loc[i] == 0);
    }
    sc[tid] = c;
    __syncthreads();
    // inclusive scan (Hillis-Steele)
    for (int off = 1; off < 1024; off <<= 1) {
        int v = sc[tid];
        int u = (tid >= off) ? sc[tid - off] : 0;
        __syncthreads();
        sc[tid] = v + u;
        __syncthreads();
    }
    int pos = sc[tid] - c;    // exclusive prefix
    if (tid == 1023) s_total = sc[1023];
#pragma unroll
    for (int i = 0; i < 16; i++) {
        if (loc[i] == 0) g_list[pos++] = tid * 16 + i;
    }
    __syncthreads();
    int total = s_total;
    if (tid == 0) g_cnt = total;
    for (int j = total + tid; j < BT; j += 1024) g_list[j] = 0;   // safe dummy
}

// ---------------------------------------------------------------------------
// Kernel P: split codebook into [h'|m'|h'] swizzled rows + c_sq (fused)
// one thread per (g, v, octet): 65536 threads
// ---------------------------------------------------------------------------
__global__ void prep_kernel(const float* __restrict__ cb) {
    int idx = blockIdx.x * blockDim.x + threadIdx.x;   // 0..65535
    int uu = idx & 7;
    int g  = (idx >> 3) & 7;
    int v  = idx >> 6;
    const float* src = cb + (size_t)v * GD + g * Dd + uu * 8;
    int c = v >> 6, r = v & 63;
    uint4* row = g_cbs + (size_t)(((g * NCHUNK + c) * CHUNK_N + r)) * KU;
    int r7 = v & 7;
    float csum = 0.f;
    uint32_t ph[4], pm[4];
#pragma unroll
    for (int j = 0; j < 4; j++) {
        float a = src[j * 2];
        float b = src[j * 2 + 1];
        csum = fmaf(a, a, csum);
        csum = fmaf(b, b, csum);
        float ha, ma, hb, mb;
        split2(a, ha, ma);
        split2(b, hb, mb);
        ph[j] = pack_bf2(ha, hb);
        pm[j] = pack_bf2(ma, mb);
    }
    uint4 H = make_uint4(ph[0], ph[1], ph[2], ph[3]);
    uint4 M = make_uint4(pm[0], pm[1], pm[2], pm[3]);
    row[(0 * 8 + uu) ^ r7] = H;   // slot0: h'
    row[(1 * 8 + uu) ^ r7] = M;   // slot1: m'
    row[(2 * 8 + uu) ^ r7] = H;   // slot2: h'
    // 8-lane butterfly over same (g,v)
#pragma unroll
    for (int off = 1; off <= 4; off <<= 1)
        csum += __shfl_xor_sync(0xffffffffu, csum, off);
    if (uu == 0) g_csq[g * Vv + v] = csum;
}

// ---------------------------------------------------------------------------
// Main VQ kernel: compacted tokens, 3-product approx GEMM + top-2 + flag
// ---------------------------------------------------------------------------
__global__ __launch_bounds__(256, 2)
void vq_kernel(const float* __restrict__ x)
{
    extern __shared__ char sm[];
    const uint32_t sbase = smem_u32(sm);
    const int tid  = threadIdx.x;
    const int wid  = tid >> 5;
    const int lane = tid & 31;
    const int g    = blockIdx.y;
    const int bt0  = blockIdx.x * TM;
    const int cnt  = g_cnt;
    if (bt0 >= cnt) return;
    float* csq_sm  = (float*)(sm + SM_CSQ);

    const char* cbs_g = (const char*)(g_cbs + (size_t)g * Vv * KU);

    // prefetch chunks 0 and 1
    {
        uint32_t dst = sbase + SM_B + (uint32_t)tid * 16;
        const char* src = cbs_g + (size_t)tid * 16;
#pragma unroll
        for (int i = 0; i < 6; i++) cp16(dst + i * 4096, src + i * 4096);
        CP_COMMIT();
#pragma unroll
        for (int i = 0; i < 6; i++)
            cp16(dst + CHUNK_B + i * 4096, src + CHUNK_B + i * 4096);
        CP_COMMIT();
    }

    // ---- build A: compacted x tile -> [h|h|m], swizzled ----
    {
#pragma unroll
        for (int it = 0; it < 4; it++) {
            int idx = it * 256 + tid;          // 0..1023
            int t = idx >> 3;                  // slot 0..127
            int o = idx & 7;                   // octet of 8 floats
            int tok = g_list[bt0 + t];         // tail slots read dummy token 0
            const float* xp = x + (size_t)tok * GD + g * Dd + o * 8;
            float4 v0 = *(const float4*)(xp);
            float4 v1 = *(const float4*)(xp + 4);
            float h0,m0,h1,m1,h2,m2,h3,m3,h4,m4,h5,m5,h6,m6,h7,m7;
            split2(v0.x,h0,m0); split2(v0.y,h1,m1);
            split2(v0.z,h2,m2); split2(v0.w,h3,m3);
            split2(v1.x,h4,m4); split2(v1.y,h5,m5);
            split2(v1.z,h6,m6); split2(v1.w,h7,m7);
            uint4 H = make_uint4(pack_bf2(h0,h1), pack_bf2(h2,h3), pack_bf2(h4,h5), pack_bf2(h6,h7));
            uint4 M = make_uint4(pack_bf2(m0,m1), pack_bf2(m2,m3), pack_bf2(m4,m5), pack_bf2(m6,m7));
            int r7 = t & 7;
            uint4* arow = (uint4*)(sm + SM_A + t * ROWB);
            arow[(0 * 8 + o) ^ r7] = H;   // slot0: h
            arow[(1 * 8 + o) ^ r7] = H;   // slot1: h
            arow[(2 * 8 + o) ^ r7] = M;   // slot2: m
        }
    }
    for (int i = tid; i < Vv; i += 256) csq_sm[i] = g_csq[g * Vv + i];
    __syncthreads();

    // ---- per-warp geometry ----
    const int wm = (wid & 3) * 32;
    const int wn = (wid >> 2) * 32;
    const int lq = lane >> 3;
    const int lr = lane & 7;
    const uint32_t aptr0 = sbase + SM_A + (uint32_t)(wm + (lq & 1) * 8 + lr) * ROWB;
    const uint32_t aptr1 = aptr0 + 16 * ROWB;
    const int aksel = lq >> 1;
    const int bksel = lq & 1;
    const uint32_t brow = (uint32_t)(wn + (lq >> 1) * 8 + lr) * ROWB;

    float mind[4], mind2[4];
    int   minv[4];
#pragma unroll
    for (int s = 0; s < 4; s++) {
        mind[s] = __int_as_float(0x7f800000);
        mind2[s] = __int_as_float(0x7f800000);
        minv[s] = 0;
    }

    for (int c = 0; c < NCHUNK; c++) {
        if (c >= 1 && c + 1 < NCHUNK) {
            uint32_t dst = sbase + SM_B + (uint32_t)(((c + 1) & 1) * CHUNK_B) + (uint32_t)tid * 16;
            const char* src = cbs_g + (size_t)(c + 1) * CHUNK_B + (size_t)tid * 16;
#pragma unroll
            for (int i = 0; i < 6; i++) cp16(dst + i * 4096, src + i * 4096);
            CP_COMMIT();
        }
        if (c + 1 < NCHUNK) { CP_WAIT(1); } else { CP_WAIT(0); }
        __syncthreads();

        float cc[2][4][4];
#pragma unroll
        for (int mt = 0; mt < 2; mt++)
#pragma unroll
            for (int nt = 0; nt < 4; nt++)
#pragma unroll
                for (int r = 0; r < 4; r++) cc[mt][nt][r] = 0.f;

        const uint32_t bptr0 = sbase + SM_B + (uint32_t)((c & 1) * CHUNK_B) + brow;
        const uint32_t bptr1 = bptr0 + 16 * ROWB;
#pragma unroll
        for (int ks = 0; ks < NKS; ks++) {
            uint32_t ua = (uint32_t)(((2 * ks + aksel) ^ lr) << 4);
            uint32_t ub = (uint32_t)(((2 * ks + bksel) ^ lr) << 4);
            uint32_t a[8], b[8];
            LDSM4(a + 0, aptr0 + ua);
            LDSM4(a + 4, aptr1 + ua);
            LDSM4(b + 0, bptr0 + ub);
            LDSM4(b + 4, bptr1 + ub);
#pragma unroll
            for (int mt = 0; mt < 2; mt++) {
                MMA(cc[mt][0], a + mt * 4, b + 0);
                MMA(cc[mt][1], a + mt * 4, b + 2);
                MMA(cc[mt][2], a + mt * 4, b + 4);
                MMA(cc[mt][3], a + mt * 4, b + 6);
            }
        }

        // dist = csq - 2*dot; running top-2 (ascending v, strict <)
        const int colb = c * CHUNK_N + wn + 2 * (lane & 3);
#pragma unroll
        for (int nt = 0; nt < 4; nt++) {
            int v0 = colb + nt * 8;
            float q0 = csq_sm[v0], q1 = csq_sm[v0 + 1];
#pragma unroll
            for (int mt = 0; mt < 2; mt++) {
                float d0 = fmaf(-2.f, cc[mt][nt][0], q0);
                float d1 = fmaf(-2.f, cc[mt][nt][1], q1);
                float d2 = fmaf(-2.f, cc[mt][nt][2], q0);
                float d3 = fmaf(-2.f, cc[mt][nt][3], q1);
                int s0 = mt * 2, s1 = mt * 2 + 1;
                if (d0 < mind[s0]) { mind2[s0] = mind[s0]; mind[s0] = d0; minv[s0] = v0; }
                else if (d0 < mind2[s0]) mind2[s0] = d0;
                if (d1 < mind[s0]) { mind2[s0] = mind[s0]; mind[s0] = d1; minv[s0] = v0 + 1; }
                else if (d1 < mind2[s0]) mind2[s0] = d1;
                if (d2 < mind[s1]) { mind2[s1] = mind[s1]; mind[s1] = d2; minv[s1] = v0; }
                else if (d2 < mind2[s1]) mind2[s1] = d2;
                if (d3 < mind[s1]) { mind2[s1] = mind[s1]; mind[s1] = d3; minv[s1] = v0 + 1; }
                else if (d3 < mind2[s1]) mind2[s1] = d3;
            }
        }
        __syncthreads();
    }

    // ---- top-2 reduce within lane-quads, write per-N-half ----
#pragma unroll
    for (int s = 0; s < 4; s++) {
        float d = mind[s], d2v = mind2[s];
        int v = minv[s];
#pragma unroll
        for (int off = 1; off <= 2; off <<= 1) {
            float o1 = __shfl_xor_sync(0xffffffffu, d, off);
            int   ov = __shfl_xor_sync(0xffffffffu, v, off);
            float o2 = __shfl_xor_sync(0xffffffffu, d2v, off);
            float big = fmaxf(d, o1);
            d2v = fminf(fminf(d2v, o2), big);
            if (o1 < d || (o1 == d && ov < v)) { d = o1; v = ov; }
        }
        if ((lane & 3) == 0) {
            int row = wm + (s >> 1) * 16 + (s & 1) * 8 + (lane >> 2);
            ((float*)(sm + SM_MD ))[(wid >> 2) * 128 + row] = d;
            ((int*)  (sm + SM_MV ))[(wid >> 2) * 128 + row] = v;
            ((float*)(sm + SM_MD2))[(wid >> 2) * 128 + row] = d2v;
        }
    }
    __syncthreads();

    // ---- combine N-halves, emit id + flag (valid tokens only) ----
    if (tid < TM && bt0 + tid < cnt) {
        float a1 = ((float*)(sm + SM_MD))[tid];
        float b1 = ((float*)(sm + SM_MD))[128 + tid];
        float a2 = ((float*)(sm + SM_MD2))[tid];
        float b2 = ((float*)(sm + SM_MD2))[128 + tid];
        int av = ((int*)(sm + SM_MV))[tid];
        int bv = ((int*)(sm + SM_MV))[128 + tid];
        float m1; int v1;
        if (b1 < a1 || (b1 == a1 && bv < av)) { m1 = b1; v1 = bv; }
        else                                  { m1 = a1; v1 = av; }
        float big = fmaxf(a1, b1);
        float m2  = fminf(fminf(a2, b2), big);
        int tok = g_list[bt0 + tid];
        int p = tok * Gg + g;
        g_ids [p] = v1;
        g_flag[p] = (m2 - m1 < DELTA) ? 1 : 0;
    }
}

// ---------------------------------------------------------------------------
// Epilogue: padded -> -1/zeros; valid -> exact-fallback, ids/quantized/loss
// 8 threads per (token, g) pair; grid 4096 x 256
// ---------------------------------------------------------------------------
__global__ __launch_bounds__(256)
void epi_kernel(const float* __restrict__ x, const int* __restrict__ pad,
                const float* __restrict__ cb, float* __restrict__ out)
{
    __shared__ float rs[256];
    const int tid  = threadIdx.x;
    const int gidx = blockIdx.x * 256 + tid;
    const int p    = gidx >> 3;
    const int sub  = gidx & 7;
    const int bt   = p >> 3;
    const int g    = p & 7;

    int pv = pad[bt];
    float ss = 0.f;

    if (pv) {
        if (sub == 0) out[p] = -1.0f;
        float4 z = make_float4(0.f, 0.f, 0.f, 0.f);
        float* qo = out + OUT_Q + (size_t)p * Dd + sub * 8;
        *(float4*)(qo)     = z;
        *(float4*)(qo + 4) = z;
    } else {
        int id = g_ids[p];
        if (g_flag[p]) {
            // exact fp32 argmin over all 1024 codewords, 8 lanes cooperate
            float xr[64];
            const float4* xp4 = (const float4*)(x + (size_t)bt * GD + g * Dd);
#pragma unroll
            for (int i = 0; i < 16; i++) {
                float4 v = xp4[i];
                xr[i*4] = v.x; xr[i*4+1] = v.y; xr[i*4+2] = v.z; xr[i*4+3] = v.w;
            }
            float bd = __int_as_float(0x7f800000);
            int bv = 0;
            for (int v = sub * 128; v < sub * 128 + 128; v++) {
                const float4* cp4 = (const float4*)(cb + (size_t)v * GD + g * Dd);
                float dot = 0.f;
#pragma unroll
                for (int i = 0; i < 16; i++) {
                    float4 cv = cp4[i];
                    dot = fmaf(cv.x, xr[i*4],   dot);
                    dot = fmaf(cv.y, xr[i*4+1], dot);
                    dot = fmaf(cv.z, xr[i*4+2], dot);
                    dot = fmaf(cv.w, xr[i*4+3], dot);
                }
                float d = fmaf(-2.f, dot, g_csq[g * Vv + v]);
                if (d < bd) { bd = d; bv = v; }
            }
            unsigned msk = 0xFFu << ((tid & 31) & ~7);
#pragma unroll
            for (int off = 1; off <= 4; off <<= 1) {
                float od = __shfl_xor_sync(msk, bd, off);
                int   ov = __shfl_xor_sync(msk, bv, off);
                if (od < bd || (od == bd && ov < bv)) { bd = od; bv = ov; }
            }
            id = bv;
        }

        if (sub == 0) out[p] = (float)id;

        int d0 = sub * 8;
        const float* qc = cb + (size_t)id * GD + g * Dd + d0;
        const float* xr = x  + (size_t)bt * GD + g * Dd + d0;
        float* qo = out + OUT_Q + (size_t)p * Dd + d0;
#pragma unroll
        for (int q4 = 0; q4 < 2; q4++) {
            float4 qv = *(const float4*)(qc + q4 * 4);
            float4 xv = *(const float4*)(xr + q4 * 4);
            float e0 = qv.x - xv.x, e1 = qv.y - xv.y, e2 = qv.z - xv.z, e3 = qv.w - xv.w;
            ss += e0*e0 + e1*e1 + e2*e2 + e3*e3;
            *(float4*)(qo + q4 * 4) = qv;   // mask == 1 here
        }
    }
    rs[tid] = ss;
    __syncthreads();
    for (int off = 128; off; off >>= 1) {
        if (tid < off) rs[tid] += rs[tid + off];
        __syncthreads();
    }
    if (tid == 0) g_partials[blockIdx.x] = rs[0];
}

// ---------------------------------------------------------------------------
// Final reduction
// ---------------------------------------------------------------------------
__global__ void final_kernel(const int* __restrict__ pad, float* __restrict__ out) {
    __shared__ float rs[1024];
    __shared__ int   rc[1024];
    int tid = threadIdx.x;
    float s = 0.f;
#pragma unroll
    for (int i = 0; i < 4; i++) s += g_partials[i * 1024 + tid];
    int c = 0;
    const int4* p4 = (const int4*)pad;
#pragma unroll
    for (int i = 0; i < 4; i++) {
        int4 v = p4[i * 1024 + tid];
        c += (v.x == 0) + (v.y == 0) + (v.z == 0) + (v.w == 0);
    }
    rs[tid] = s; rc[tid] = c;
    __syncthreads();
    for (int off = 512; off; off >>= 1) {
        if (tid < off) { rs[tid] += rs[tid + off]; rc[tid] += rc[tid + off]; }
        __syncthreads();
    }
    if (tid == 0) {
        float k = rs[0] / (float)rc[0];
        out[OUT_LOSS + 0] = k;
        out[OUT_LOSS + 1] = k;
        out[OUT_LOSS + 2] = k + k;
    }
}

// ---------------------------------------------------------------------------
extern "C" void kernel_launch(void* const* d_in, const int* in_sizes, int n_in,
                              void* d_out, int out_size)
{
    const float* x   = (const float*)d_in[0];
    const int*   pad = (const int*)  d_in[1];
    const float* cb  = (const float*)d_in[2];
    float*       out = (float*)d_out;

    cudaFuncSetAttribute(vq_kernel, cudaFuncAttributeMaxDynamicSharedMemorySize, SMEM_TOTAL);

    scan_kernel<<<1, 1024>>>(pad);
    prep_kernel<<<256, 256>>>(cb);
    dim3 grid(BT / TM, Gg);
    vq_kernel<<<grid, 256, SMEM_TOTAL>>>(x);
    epi_kernel<<<4096, 256>>>(x, pad, cb, out);
    final_kernel<<<1, 1024>>>(pad, out);
}

// round 12
// speedup vs baseline: 2.3849x; 1.1345x over previous
#include <cuda_runtime.h>
#include <cuda_bf16.h>
#include <cstdint>

// ---------------- problem constants ----------------
#define BT   16384
#define Gg   8
#define Dd   64
#define Vv   1024
#define GD   512
#define TM   128            // tokens per CTA
#define N_IDS (BT*Gg)
#define OUT_Q N_IDS
#define OUT_LOSS (N_IDS + BT*GD)
#define DELTA 0.012f

// 3-slot extended-K layout: A=[h|h|m], B=[h'|m'|h'], 3 x 64 bf16 = 24 x 16B/row
#define KU    24
#define ROWB  384
#define NKS   12
#define CHUNK_N 64
#define NCHUNK  16
#define CHUNK_B (CHUNK_N*ROWB)   // 24576

// ---------------- smem layout (bytes) ----------------
#define SM_A    0            // 128 x 384 = 49152
#define SM_B    49152        // 2 x 24576 = 49152
#define SM_CSQ  98304        // 1024 f32
#define SM_MD   102400       // 256 f32
#define SM_MV   103424       // 256 i32
#define SM_MD2  104448       // 256 f32
#define SMEM_TOTAL 105472

// ---------------- device globals ----------------
__device__ float g_csq[Gg*Vv];
__device__ float g_partials[4096];
__device__ int   g_ids [BT*Gg];
__device__ int   g_flag[BT*Gg];
__device__ int   g_list[BT];
__device__ int   g_cnt;
__device__ __align__(16) uint4 g_cbs[Gg*Vv*KU];   // 3 MB

// ---------------- PTX helpers ----------------
__device__ __forceinline__ uint32_t smem_u32(const void* p) {
    uint32_t a;
    asm("{ .reg .u64 t; cvta.to.shared.u64 t, %1; cvt.u32.u64 %0, t; }" : "=r"(a) : "l"(p));
    return a;
}
#define LDSM4(r, addr) \
    asm volatile("ldmatrix.sync.aligned.m8n8.x4.shared.b16 {%0,%1,%2,%3}, [%4];" \
        : "=r"((r)[0]), "=r"((r)[1]), "=r"((r)[2]), "=r"((r)[3]) : "r"(addr))
#define MMA(c, a, b) \
    asm volatile("mma.sync.aligned.m16n8k16.row.col.f32.bf16.bf16.f32 " \
        "{%0,%1,%2,%3},{%4,%5,%6,%7},{%8,%9},{%0,%1,%2,%3};" \
        : "+f"((c)[0]), "+f"((c)[1]), "+f"((c)[2]), "+f"((c)[3]) \
        : "r"((a)[0]), "r"((a)[1]), "r"((a)[2]), "r"((a)[3]), "r"((b)[0]), "r"((b)[1]))
__device__ __forceinline__ void cp16(uint32_t dst, const void* src) {
    asm volatile("cp.async.cg.shared.global [%0], [%1], 16;" :: "r"(dst), "l"(src) : "memory");
}
#define CP_COMMIT()  asm volatile("cp.async.commit_group;" ::: "memory")
#define CP_WAIT(n)   asm volatile("cp.async.wait_group %0;" :: "n"(n) : "memory")

__device__ __forceinline__ void split2(float v, float& h, float& m) {
    h = __bfloat162float(__float2bfloat16_rn(v));
    m = v - h;   // bf16-rounded at pack time
}
__device__ __forceinline__ uint32_t pack_bf2(float lo, float hi) {
    uint32_t u;
    asm("cvt.rn.bf16x2.f32 %0, %1, %2;" : "=r"(u) : "f"(hi), "f"(lo));
    return u;
}

// ---------------------------------------------------------------------------
// Kernel S: deterministic compaction of valid tokens (warp-shuffle scan)
// 1 block, 1024 threads, 16 tokens each
// ---------------------------------------------------------------------------
__global__ void scan_kernel(const int* __restrict__ pad) {
    __shared__ int wsum[32];
    __shared__ int s_total;
    const int tid  = threadIdx.x;
    const int lane = tid & 31;
    const int w    = tid >> 5;
    int loc[16];
    int c = 0;
#pragma unroll
    for (int i = 0; i < 16; i++) {
        loc[i] = pad[tid * 16 + i];
        c += (loc[i] == 0);
    }
    // warp inclusive scan
    int sc = c;
#pragma unroll
    for (int off = 1; off < 32; off <<= 1) {
        int n = __shfl_up_sync(0xffffffffu, sc, off);
        if (lane >= off) sc += n;
    }
    if (lane == 31) wsum[w] = sc;
    __syncthreads();
    if (w == 0) {
        int v = wsum[lane];
#pragma unroll
        for (int off = 1; off < 32; off <<= 1) {
            int n = __shfl_up_sync(0xffffffffu, v, off);
            if (lane >= off) v += n;
        }
        wsum[lane] = v;
        if (lane == 31) s_total = v;
    }
    __syncthreads();
    int pos = (w ? wsum[w - 1] : 0) + sc - c;   // exclusive prefix
#pragma unroll
    for (int i = 0; i < 16; i++) {
        if (loc[i] == 0) g_list[pos++] = tid * 16 + i;
    }
    int total = s_total;
    if (tid == 0) g_cnt = total;
    for (int j = total + tid; j < BT; j += 1024) g_list[j] = 0;   // safe dummy
}

// ---------------------------------------------------------------------------
// Kernel P: split codebook into [h'|m'|h'] swizzled rows + c_sq (fused)
// ---------------------------------------------------------------------------
__global__ void prep_kernel(const float* __restrict__ cb) {
    int idx = blockIdx.x * blockDim.x + threadIdx.x;   // 0..65535
    int uu = idx & 7;
    int g  = (idx >> 3) & 7;
    int v  = idx >> 6;
    const float* src = cb + (size_t)v * GD + g * Dd + uu * 8;
    int c = v >> 6, r = v & 63;
    uint4* row = g_cbs + (size_t)(((g * NCHUNK + c) * CHUNK_N + r)) * KU;
    int r7 = v & 7;
    float csum = 0.f;
    uint32_t ph[4], pm[4];
#pragma unroll
    for (int j = 0; j < 4; j++) {
        float a = src[j * 2];
        float b = src[j * 2 + 1];
        csum = fmaf(a, a, csum);
        csum = fmaf(b, b, csum);
        float ha, ma, hb, mb;
        split2(a, ha, ma);
        split2(b, hb, mb);
        ph[j] = pack_bf2(ha, hb);
        pm[j] = pack_bf2(ma, mb);
    }
    uint4 H = make_uint4(ph[0], ph[1], ph[2], ph[3]);
    uint4 M = make_uint4(pm[0], pm[1], pm[2], pm[3]);
    row[(0 * 8 + uu) ^ r7] = H;   // slot0: h'
    row[(1 * 8 + uu) ^ r7] = M;   // slot1: m'
    row[(2 * 8 + uu) ^ r7] = H;   // slot2: h'
#pragma unroll
    for (int off = 1; off <= 4; off <<= 1)
        csum += __shfl_xor_sync(0xffffffffu, csum, off);
    if (uu == 0) g_csq[g * Vv + v] = csum;
}

// ---------------------------------------------------------------------------
// Main VQ kernel: compacted tokens, 3-product approx GEMM + top-2 + flag
// ---------------------------------------------------------------------------
__global__ __launch_bounds__(256, 2)
void vq_kernel(const float* __restrict__ x)
{
    extern __shared__ char sm[];
    const uint32_t sbase = smem_u32(sm);
    const int tid  = threadIdx.x;
    const int wid  = tid >> 5;
    const int lane = tid & 31;
    const int g    = blockIdx.y;
    const int bt0  = blockIdx.x * TM;
    const int cnt  = g_cnt;
    if (bt0 >= cnt) return;
    float* csq_sm  = (float*)(sm + SM_CSQ);

    const char* cbs_g = (const char*)(g_cbs + (size_t)g * Vv * KU);

    // prefetch chunks 0 and 1
    {
        uint32_t dst = sbase + SM_B + (uint32_t)tid * 16;
        const char* src = cbs_g + (size_t)tid * 16;
#pragma unroll
        for (int i = 0; i < 6; i++) cp16(dst + i * 4096, src + i * 4096);
        CP_COMMIT();
#pragma unroll
        for (int i = 0; i < 6; i++)
            cp16(dst + CHUNK_B + i * 4096, src + CHUNK_B + i * 4096);
        CP_COMMIT();
    }

    // ---- build A: compacted x tile -> [h|h|m], swizzled ----
    {
#pragma unroll
        for (int it = 0; it < 4; it++) {
            int idx = it * 256 + tid;          // 0..1023
            int t = idx >> 3;                  // slot 0..127
            int o = idx & 7;                   // octet of 8 floats
            int tok = g_list[bt0 + t];         // tail slots read dummy token 0
            const float* xp = x + (size_t)tok * GD + g * Dd + o * 8;
            float4 v0 = *(const float4*)(xp);
            float4 v1 = *(const float4*)(xp + 4);
            float h0,m0,h1,m1,h2,m2,h3,m3,h4,m4,h5,m5,h6,m6,h7,m7;
            split2(v0.x,h0,m0); split2(v0.y,h1,m1);
            split2(v0.z,h2,m2); split2(v0.w,h3,m3);
            split2(v1.x,h4,m4); split2(v1.y,h5,m5);
            split2(v1.z,h6,m6); split2(v1.w,h7,m7);
            uint4 H = make_uint4(pack_bf2(h0,h1), pack_bf2(h2,h3), pack_bf2(h4,h5), pack_bf2(h6,h7));
            uint4 M = make_uint4(pack_bf2(m0,m1), pack_bf2(m2,m3), pack_bf2(m4,m5), pack_bf2(m6,m7));
            int r7 = t & 7;
            uint4* arow = (uint4*)(sm + SM_A + t * ROWB);
            arow[(0 * 8 + o) ^ r7] = H;   // slot0: h
            arow[(1 * 8 + o) ^ r7] = H;   // slot1: h
            arow[(2 * 8 + o) ^ r7] = M;   // slot2: m
        }
    }
    for (int i = tid; i < Vv; i += 256) csq_sm[i] = g_csq[g * Vv + i];
    __syncthreads();

    // ---- per-warp geometry ----
    const int wm = (wid & 3) * 32;
    const int wn = (wid >> 2) * 32;
    const int lq = lane >> 3;
    const int lr = lane & 7;
    const uint32_t aptr0 = sbase + SM_A + (uint32_t)(wm + (lq & 1) * 8 + lr) * ROWB;
    const uint32_t aptr1 = aptr0 + 16 * ROWB;
    const int aksel = lq >> 1;
    const int bksel = lq & 1;
    const uint32_t brow = (uint32_t)(wn + (lq >> 1) * 8 + lr) * ROWB;

    float mind[4], mind2[4];
    int   minv[4];
#pragma unroll
    for (int s = 0; s < 4; s++) {
        mind[s] = __int_as_float(0x7f800000);
        mind2[s] = __int_as_float(0x7f800000);
        minv[s] = 0;
    }

    for (int c = 0; c < NCHUNK; c++) {
        if (c >= 1 && c + 1 < NCHUNK) {
            uint32_t dst = sbase + SM_B + (uint32_t)(((c + 1) & 1) * CHUNK_B) + (uint32_t)tid * 16;
            const char* src = cbs_g + (size_t)(c + 1) * CHUNK_B + (size_t)tid * 16;
#pragma unroll
            for (int i = 0; i < 6; i++) cp16(dst + i * 4096, src + i * 4096);
            CP_COMMIT();
        }
        if (c + 1 < NCHUNK) { CP_WAIT(1); } else { CP_WAIT(0); }
        __syncthreads();

        float cc[2][4][4];
#pragma unroll
        for (int mt = 0; mt < 2; mt++)
#pragma unroll
            for (int nt = 0; nt < 4; nt++)
#pragma unroll
                for (int r = 0; r < 4; r++) cc[mt][nt][r] = 0.f;

        const uint32_t bptr0 = sbase + SM_B + (uint32_t)((c & 1) * CHUNK_B) + brow;
        const uint32_t bptr1 = bptr0 + 16 * ROWB;
#pragma unroll
        for (int ks = 0; ks < NKS; ks++) {
            uint32_t ua = (uint32_t)(((2 * ks + aksel) ^ lr) << 4);
            uint32_t ub = (uint32_t)(((2 * ks + bksel) ^ lr) << 4);
            uint32_t a[8], b[8];
            LDSM4(a + 0, aptr0 + ua);
            LDSM4(a + 4, aptr1 + ua);
            LDSM4(b + 0, bptr0 + ub);
            LDSM4(b + 4, bptr1 + ub);
#pragma unroll
            for (int mt = 0; mt < 2; mt++) {
                MMA(cc[mt][0], a + mt * 4, b + 0);
                MMA(cc[mt][1], a + mt * 4, b + 2);
                MMA(cc[mt][2], a + mt * 4, b + 4);
                MMA(cc[mt][3], a + mt * 4, b + 6);
            }
        }

        // dist = csq - 2*dot; running top-2 (ascending v, strict <)
        const int colb = c * CHUNK_N + wn + 2 * (lane & 3);
#pragma unroll
        for (int nt = 0; nt < 4; nt++) {
            int v0 = colb + nt * 8;
            float q0 = csq_sm[v0], q1 = csq_sm[v0 + 1];
#pragma unroll
            for (int mt = 0; mt < 2; mt++) {
                float d0 = fmaf(-2.f, cc[mt][nt][0], q0);
                float d1 = fmaf(-2.f, cc[mt][nt][1], q1);
                float d2 = fmaf(-2.f, cc[mt][nt][2], q0);
                float d3 = fmaf(-2.f, cc[mt][nt][3], q1);
                int s0 = mt * 2, s1 = mt * 2 + 1;
                if (d0 < mind[s0]) { mind2[s0] = mind[s0]; mind[s0] = d0; minv[s0] = v0; }
                else if (d0 < mind2[s0]) mind2[s0] = d0;
                if (d1 < mind[s0]) { mind2[s0] = mind[s0]; mind[s0] = d1; minv[s0] = v0 + 1; }
                else if (d1 < mind2[s0]) mind2[s0] = d1;
                if (d2 < mind[s1]) { mind2[s1] = mind[s1]; mind[s1] = d2; minv[s1] = v0; }
                else if (d2 < mind2[s1]) mind2[s1] = d2;
                if (d3 < mind[s1]) { mind2[s1] = mind[s1]; mind[s1] = d3; minv[s1] = v0 + 1; }
                else if (d3 < mind2[s1]) mind2[s1] = d3;
            }
        }
        __syncthreads();
    }

    // ---- top-2 reduce within lane-quads, write per-N-half ----
#pragma unroll
    for (int s = 0; s < 4; s++) {
        float d = mind[s], d2v = mind2[s];
        int v = minv[s];
#pragma unroll
        for (int off = 1; off <= 2; off <<= 1) {
            float o1 = __shfl_xor_sync(0xffffffffu, d, off);
            int   ov = __shfl_xor_sync(0xffffffffu, v, off);
            float o2 = __shfl_xor_sync(0xffffffffu, d2v, off);
            float big = fmaxf(d, o1);
            d2v = fminf(fminf(d2v, o2), big);
            if (o1 < d || (o1 == d && ov < v)) { d = o1; v = ov; }
        }
        if ((lane & 3) == 0) {
            int row = wm + (s >> 1) * 16 + (s & 1) * 8 + (lane >> 2);
            ((float*)(sm + SM_MD ))[(wid >> 2) * 128 + row] = d;
            ((int*)  (sm + SM_MV ))[(wid >> 2) * 128 + row] = v;
            ((float*)(sm + SM_MD2))[(wid >> 2) * 128 + row] = d2v;
        }
    }
    __syncthreads();

    // ---- combine N-halves, emit id + flag (valid tokens only) ----
    if (tid < TM && bt0 + tid < cnt) {
        float a1 = ((float*)(sm + SM_MD))[tid];
        float b1 = ((float*)(sm + SM_MD))[128 + tid];
        float a2 = ((float*)(sm + SM_MD2))[tid];
        float b2 = ((float*)(sm + SM_MD2))[128 + tid];
        int av = ((int*)(sm + SM_MV))[tid];
        int bv = ((int*)(sm + SM_MV))[128 + tid];
        float m1; int v1;
        if (b1 < a1 || (b1 == a1 && bv < av)) { m1 = b1; v1 = bv; }
        else                                  { m1 = a1; v1 = av; }
        float big = fmaxf(a1, b1);
        float m2  = fminf(fminf(a2, b2), big);
        int tok = g_list[bt0 + tid];
        int p = tok * Gg + g;
        g_ids [p] = v1;
        g_flag[p] = (m2 - m1 < DELTA) ? 1 : 0;
    }
}

// ---------------------------------------------------------------------------
// Kernel F: exact fp32 rescan for flagged pairs (one warp per pair)
// grid 16384 x 256 (8 warps/block); non-flagged warps exit after one load
// ---------------------------------------------------------------------------
__global__ __launch_bounds__(256)
void fix_kernel(const float* __restrict__ x, const float* __restrict__ cb)
{
    __shared__ float xs[8][64];
    const int wid  = threadIdx.x >> 5;
    const int lane = threadIdx.x & 31;
    const int p    = blockIdx.x * 8 + wid;
    if (!g_flag[p]) return;    // padded pairs: flag stays 0 (zero-init, never set)
    const int bt = p >> 3;
    const int g  = p & 7;

    // stage x row into smem (warp-local)
    const float4* xr4 = (const float4*)(x + (size_t)bt * GD + g * Dd);
    if (lane < 16) ((float4*)xs[wid])[lane] = xr4[lane];
    __syncwarp();

    float bd = __int_as_float(0x7f800000);
    int   bv = 0;
#pragma unroll 1
    for (int v = lane; v < Vv; v += 32) {
        const float4* cp4 = (const float4*)(cb + (size_t)v * GD + g * Dd);
        float dot = 0.f;
#pragma unroll
        for (int i = 0; i < 16; i++) {
            float4 cv = cp4[i];
            dot = fmaf(cv.x, xs[wid][i*4],   dot);
            dot = fmaf(cv.y, xs[wid][i*4+1], dot);
            dot = fmaf(cv.z, xs[wid][i*4+2], dot);
            dot = fmaf(cv.w, xs[wid][i*4+3], dot);
        }
        float d = fmaf(-2.f, dot, g_csq[g * Vv + v]);
        if (d < bd) { bd = d; bv = v; }
    }
#pragma unroll
    for (int off = 16; off >= 1; off >>= 1) {
        float od = __shfl_xor_sync(0xffffffffu, bd, off);
        int   ov = __shfl_xor_sync(0xffffffffu, bv, off);
        if (od < bd || (od == bd && ov < bv)) { bd = od; bv = ov; }
    }
    if (lane == 0) g_ids[p] = bv;
}

// ---------------------------------------------------------------------------
// Lean epilogue: padded -> -1/zeros; valid -> gather quantized + loss partial
// 8 threads per (token, g) pair; grid 4096 x 256
// ---------------------------------------------------------------------------
__global__ __launch_bounds__(256)
void epi_kernel(const float* __restrict__ x, const int* __restrict__ pad,
                const float* __restrict__ cb, float* __restrict__ out)
{
    __shared__ float rs[256];
    const int tid  = threadIdx.x;
    const int gidx = blockIdx.x * 256 + tid;
    const int p    = gidx >> 3;
    const int sub  = gidx & 7;
    const int bt   = p >> 3;
    const int g    = p & 7;

    int pv = pad[bt];
    float ss = 0.f;

    if (pv) {
        if (sub == 0) out[p] = -1.0f;
        float4 z = make_float4(0.f, 0.f, 0.f, 0.f);
        float* qo = out + OUT_Q + (size_t)p * Dd + sub * 8;
        *(float4*)(qo)     = z;
        *(float4*)(qo + 4) = z;
    } else {
        int id = g_ids[p];
        if (sub == 0) out[p] = (float)id;
        int d0 = sub * 8;
        const float* qc = cb + (size_t)id * GD + g * Dd + d0;
        const float* xr = x  + (size_t)bt * GD + g * Dd + d0;
        float* qo = out + OUT_Q + (size_t)p * Dd + d0;
#pragma unroll
        for (int q4 = 0; q4 < 2; q4++) {
            float4 qv = *(const float4*)(qc + q4 * 4);
            float4 xv = *(const float4*)(xr + q4 * 4);
            float e0 = qv.x - xv.x, e1 = qv.y - xv.y, e2 = qv.z - xv.z, e3 = qv.w - xv.w;
            ss += e0*e0 + e1*e1 + e2*e2 + e3*e3;
            *(float4*)(qo + q4 * 4) = qv;   // mask == 1 here
        }
    }
    rs[tid] = ss;
    __syncthreads();
    for (int off = 128; off; off >>= 1) {
        if (tid < off) rs[tid] += rs[tid + off];
        __syncthreads();
    }
    if (tid == 0) g_partials[blockIdx.x] = rs[0];
}

// ---------------------------------------------------------------------------
// Final reduction (denominator = g_cnt from scan)
// ---------------------------------------------------------------------------
__global__ void final_kernel(float* __restrict__ out) {
    __shared__ float rs[1024];
    int tid = threadIdx.x;
    float s = 0.f;
#pragma unroll
    for (int i = 0; i < 4; i++) s += g_partials[i * 1024 + tid];
    rs[tid] = s;
    __syncthreads();
    for (int off = 512; off; off >>= 1) {
        if (tid < off) rs[tid] += rs[tid + off];
        __syncthreads();
    }
    if (tid == 0) {
        float k = rs[0] / (float)g_cnt;
        out[OUT_LOSS + 0] = k;
        out[OUT_LOSS + 1] = k;
        out[OUT_LOSS + 2] = k + k;
    }
}

// ---------------------------------------------------------------------------
extern "C" void kernel_launch(void* const* d_in, const int* in_sizes, int n_in,
                              void* d_out, int out_size)
{
    const float* x   = (const float*)d_in[0];
    const int*   pad = (const int*)  d_in[1];
    const float* cb  = (const float*)d_in[2];
    float*       out = (float*)d_out;

    cudaFuncSetAttribute(vq_kernel, cudaFuncAttributeMaxDynamicSharedMemorySize, SMEM_TOTAL);

    scan_kernel<<<1, 1024>>>(pad);
    prep_kernel<<<256, 256>>>(cb);
    dim3 grid(BT / TM, Gg);
    vq_kernel<<<grid, 256, SMEM_TOTAL>>>(x);
    fix_kernel<<<N_IDS / 8, 256>>>(x, cb);
    epi_kernel<<<4096, 256>>>(x, pad, cb, out);
    final_kernel<<<1, 1024>>>(out);
}